// round 15
// baseline (speedup 1.0000x reference)
#include <cuda_runtime.h>
#include <cuda_bf16.h>
#include <math.h>

#define BB 8
#define LL 8192
#define CCH 256
#define NN 512
#define KK 16
#define FMINF 1.17549435e-38f
#define NC 24

// scratch (no allocations allowed)
__device__ float g_w[BB * NN];               // FTZ proto_weights
__device__ float g_pn2[NN];                  // |p_n|^2
__device__ float g_qq[BB * LL];              // |q_l|^2
__device__ unsigned g_Pz[NN * 128];          // bf16x2, fragment-permuted P
__device__ unsigned g_Qz[BB * LL * 128];     // bf16x2, fragment-permuted Q (32MB)
__device__ int g_cc[BB * LL];                // per-row candidate count
__device__ int g_cand[BB * LL * NC];         // per-row candidate indices

__device__ __forceinline__ float warp_sumf(float v) {
    #pragma unroll
    for (int o = 16; o; o >>= 1) v += __shfl_xor_sync(0xffffffffu, v, o);
    return v;
}
__device__ __forceinline__ double warp_sumd(double v) {
    #pragma unroll
    for (int o = 16; o; o >>= 1) v += __shfl_xor_sync(0xffffffffu, v, o);
    return v;
}

__device__ __forceinline__ void mma_bf16(float& c0, float& c1, float& c2, float& c3,
                                         unsigned a0, unsigned a1, unsigned a2,
                                         unsigned a3, unsigned b0, unsigned b1) {
    asm volatile(
        "mma.sync.aligned.m16n8k16.row.col.f32.bf16.bf16.f32 "
        "{%0,%1,%2,%3}, {%4,%5,%6,%7}, {%8,%9}, {%0,%1,%2,%3};"
        : "+f"(c0), "+f"(c1), "+f"(c2), "+f"(c3)
        : "r"(a0), "r"(a1), "r"(a2), "r"(a3), "r"(b0), "r"(b1));
}

__device__ __forceinline__ float dot8(const float4& qa, const float4& qb,
                                      const float4& pa, const float4& pb) {
    float s = 0.f;
    s = fmaf(qa.x, pa.x, s); s = fmaf(qa.y, pa.y, s);
    s = fmaf(qa.z, pa.z, s); s = fmaf(qa.w, pa.w, s);
    s = fmaf(qb.x, pb.x, s); s = fmaf(qb.y, pb.y, s);
    s = fmaf(qb.z, pb.z, s); s = fmaf(qb.w, pb.w, s);
    return s;
}

__device__ __forceinline__ unsigned packbf(float x, float y) {
    __nv_bfloat162 h = __floats2bfloat162_rn(x, y);
    return *(unsigned*)&h;
}

// ---------------------------------------------------------------------------
// prep: per-batch FTZ proto weights (unchanged semantics)
// ---------------------------------------------------------------------------
__global__ void prep_w_kernel(const float* __restrict__ P,
                              const float* __restrict__ gt) {
    int b = blockIdx.x;
    int tid = threadIdx.x;
    int lane = tid & 31, wid = tid >> 5;
    __shared__ double gsd[CCH];
    __shared__ float xs[NN];
    __shared__ float redf[256];
    __shared__ double redd[256];
    __shared__ float sXmax, sZw;

    if (tid < CCH) {
        double s = 0.0;
        #pragma unroll
        for (int k = 0; k < KK; k++) s += (double)gt[(b * KK + k) * CCH + tid];
        gsd[tid] = (double)__fdiv_rn((float)s, 16.0f);
    }
    __syncthreads();

    for (int n = wid; n < NN; n += 8) {
        const float4* pr4 = (const float4*)(P + n * CCH);
        float4 v0 = pr4[lane];
        float4 v1 = pr4[lane + 32];
        int c0 = lane * 4, c1 = 128 + lane * 4;
        double a = 0.0;
        a = fma((double)v0.x, gsd[c0 + 0], a);
        a = fma((double)v0.y, gsd[c0 + 1], a);
        a = fma((double)v0.z, gsd[c0 + 2], a);
        a = fma((double)v0.w, gsd[c0 + 3], a);
        a = fma((double)v1.x, gsd[c1 + 0], a);
        a = fma((double)v1.y, gsd[c1 + 1], a);
        a = fma((double)v1.z, gsd[c1 + 2], a);
        a = fma((double)v1.w, gsd[c1 + 3], a);
        a = warp_sumd(a);
        if (lane == 0) xs[n] = __fdiv_rn((float)a, 0.1f);
    }
    __syncthreads();

    {
        float m = -INFINITY;
        for (int n = tid; n < NN; n += blockDim.x) m = fmaxf(m, xs[n]);
        redf[tid] = m;
        __syncthreads();
        for (int s = 128; s; s >>= 1) {
            if (tid < s) redf[tid] = fmaxf(redf[tid], redf[tid + s]);
            __syncthreads();
        }
        if (tid == 0) sXmax = redf[0];
        __syncthreads();
    }
    float X = sXmax;

    {
        double z = 0.0;
        for (int n = tid; n < NN; n += blockDim.x) {
            float e = expf(__fsub_rn(xs[n], X));
            if (e >= FMINF) z += (double)e;
        }
        redd[tid] = z;
        __syncthreads();
        for (int s = 128; s; s >>= 1) {
            if (tid < s) redd[tid] += redd[tid + s];
            __syncthreads();
        }
        if (tid == 0) sZw = (float)redd[0];
        __syncthreads();
    }
    float Zw = sZw;

    for (int n = tid; n < NN; n += blockDim.x) {
        float e = expf(__fsub_rn(xs[n], X));
        if (e < FMINF) e = 0.f;
        float w = __fdiv_rn(e, Zw);
        if (w < FMINF) w = 0.f;
        g_w[b * NN + n] = w;
    }
}

// ---------------------------------------------------------------------------
// prep: bf16-convert + fragment-permute P/Q (+ norms). 128 u32 per row.
// ---------------------------------------------------------------------------
__global__ void prep_pz_kernel(const float* __restrict__ P) {
    int lane = threadIdx.x & 31, wid = threadIdx.x >> 5;
    int row = blockIdx.x * 8 + wid;
    const float4* p4 = (const float4*)(P + (size_t)row * CCH);
    float4 v0 = p4[lane], v1 = p4[lane + 32];
    float s = warp_sumf(dot8(v0, v1, v0, v1));
    if (lane == 0) g_pn2[row] = s;

    unsigned* dst = g_Pz + (size_t)row * 128;
    int gq = lane >> 2, f = lane & 3;
    int w1 = (f < 2) ? 4 * f : 4 * f - 7;
    int w2 = (f < 2) ? 4 * f + 2 : 4 * f - 5;
    dst[gq * 8 + w1] = packbf(v0.x, v0.y);
    dst[gq * 8 + w2] = packbf(v0.z, v0.w);
    dst[(gq + 8) * 8 + w1] = packbf(v1.x, v1.y);
    dst[(gq + 8) * 8 + w2] = packbf(v1.z, v1.w);
}

__global__ void prep_qz_kernel(const float* __restrict__ Q) {
    int lane = threadIdx.x & 31, wid = threadIdx.x >> 5;
    int row = blockIdx.x * 8 + wid;
    const float4* q4 = (const float4*)(Q + (size_t)row * CCH);
    float4 v0 = q4[lane], v1 = q4[lane + 32];
    float s = warp_sumf(dot8(v0, v1, v0, v1));
    if (lane == 0) g_qq[row] = s;

    unsigned* dst = g_Qz + (size_t)row * 128;
    int gq = lane >> 2, f = lane & 3;
    int w1 = (f < 2) ? 4 * f : 4 * f - 7;
    int w2 = (f < 2) ? 4 * f + 2 : 4 * f - 5;
    dst[gq * 8 + w1] = packbf(v0.x, v0.y);
    dst[gq * 8 + w2] = packbf(v0.z, v0.w);
    dst[(gq + 8) * 8 + w1] = packbf(v1.x, v1.y);
    dst[(gq + 8) * 8 + w2] = packbf(v1.z, v1.w);
}

// ---------------------------------------------------------------------------
// Filter kernel: bf16 mma, block = 16 rows x 512 protos, 256 thr (8 warps =
// 8 N-octants), warp = 16L x 64N => 32 accumulators. Barrier-free mainloop,
// B from L2-resident g_Pz. Emits per-row candidate lists to global.
// ---------------------------------------------------------------------------
struct __align__(16) FilterSmem {
    unsigned q_s[16][136];   // bf16 Q tile, padded stride (8.7 KB)
    float dmS[8][16];
    int cnt[16];
    int cand[16][NC];
};

__global__ void __launch_bounds__(256, 3)
filter_kernel(float* __restrict__ dummy) {
    __shared__ FilterSmem S;

    int tid = threadIdx.x;
    int lane = tid & 31, w = tid >> 5;   // w = N-octant
    int g = lane >> 2, q = lane & 3;

    int R0 = blockIdx.x * 16;

    // stage Q tile: 16 rows x 32 uint4 = 512 uint4
    #pragma unroll
    for (int r = 0; r < 2; r++) {
        int idx = tid + r * 256;
        int l = idx >> 5, j = idx & 31;
        uint4 v = ((const uint4*)(g_Qz + (size_t)(R0 + l) * 128))[j];
        *(uint4*)&S.q_s[l][j * 4] = v;
    }
    if (tid < 16) { S.cnt[tid] = 1; S.cand[tid][0] = 0; }
    __syncthreads();

    float acc[8][4];
    #pragma unroll
    for (int ns = 0; ns < 8; ns++)
        #pragma unroll
        for (int e = 0; e < 4; e++) acc[ns][e] = 0.f;

    #pragma unroll 1
    for (int cc = 0; cc < 8; cc++) {
        #pragma unroll
        for (int grp = 0; grp < 2; grp++) {
            int wo = cc * 16 + grp * 8 + 2 * q;
            uint2 Bv[8];
            #pragma unroll
            for (int ns = 0; ns < 8; ns++) {
                int n = w * 64 + ns * 8 + g;
                Bv[ns] = __ldg((const uint2*)(g_Pz + (size_t)n * 128 + wo));
            }
            uint2 A0 = *(const uint2*)&S.q_s[g][wo];
            uint2 A1 = *(const uint2*)&S.q_s[g + 8][wo];
            #pragma unroll
            for (int ns = 0; ns < 8; ns++)
                mma_bf16(acc[ns][0], acc[ns][1], acc[ns][2], acc[ns][3],
                         A0.x, A1.x, A0.y, A1.y, Bv[ns].x, Bv[ns].y);
        }
    }

    // Phase 1: per-(octant,row) local max
    #pragma unroll
    for (int h = 0; h < 2; h++) {
        int r = 8 * h + g;
        float vm = -INFINITY;
        #pragma unroll
        for (int ns = 0; ns < 8; ns++)
            #pragma unroll
            for (int e = 0; e < 2; e++)
                vm = fmaxf(vm, acc[ns][2 * h + e]);
        vm = fmaxf(vm, __shfl_xor_sync(0xffffffffu, vm, 1));
        vm = fmaxf(vm, __shfl_xor_sync(0xffffffffu, vm, 2));
        if (q == 0) S.dmS[w][r] = vm;
    }
    __syncthreads();

    // Phase 2: candidate push (approx dot within 9.9 of approx max)
    #pragma unroll
    for (int h = 0; h < 2; h++) {
        int r = 8 * h + g;
        float gdm = -INFINITY;
        #pragma unroll
        for (int o = 0; o < 8; o++) gdm = fmaxf(gdm, S.dmS[o][r]);
        float dthr = gdm - 9.9f;
        #pragma unroll
        for (int ns = 0; ns < 8; ns++)
            #pragma unroll
            for (int e = 0; e < 2; e++) {
                float v = acc[ns][2 * h + e];
                int n = w * 64 + ns * 8 + 2 * q + e;
                if (n != 0 && v > dthr) {
                    int slot = atomicAdd(&S.cnt[r], 1);
                    if (slot < NC) S.cand[r][slot] = n;
                }
            }
    }
    __syncthreads();

    // copy lists out
    if (tid < 16) g_cc[R0 + tid] = S.cnt[tid];
    for (int idx = tid; idx < 16 * NC; idx += 256) {
        int r = idx / NC, i = idx % NC;
        if (i < min(S.cnt[r], NC)) g_cand[(size_t)(R0 + r) * NC + i] = S.cand[r][i];
    }
}

// ---------------------------------------------------------------------------
// Refine kernel: one warp per row. Exact f32 dots + FTZ chain (unchanged).
// ---------------------------------------------------------------------------
__global__ void __launch_bounds__(256, 6)
refine_kernel(const float* __restrict__ Q, const float* __restrict__ P,
              float* __restrict__ out) {
    __shared__ float candd[8][NC];
    __shared__ float ovf[8][NN];    // overflow scratch (rarely used)

    int lane = threadIdx.x & 31, w = threadIdx.x >> 5;
    int row = blockIdx.x * 8 + w;
    int b = row >> 13;
    int cntr = g_cc[row];

    const float4* q4 = (const float4*)(Q + (size_t)row * CCH);
    float4 qa = q4[lane], qb = q4[lane + 32];

    int bn = 0;
    float bp = 0.f;
    float bd;

    if (cntr <= NC) {
        int m = cntr;
        #pragma unroll 1
        for (int i0 = 0; i0 < m; i0 += 4) {
            int mm = min(4, m - i0);
            float4 pa[4], pb[4];
            #pragma unroll
            for (int j = 0; j < 4; j++)
                if (j < mm) {
                    const float4* p4 =
                        (const float4*)(P + g_cand[(size_t)row * NC + i0 + j] * CCH);
                    pa[j] = p4[lane];
                    pb[j] = p4[lane + 32];
                }
            float s[4];
            #pragma unroll
            for (int j = 0; j < 4; j++)
                if (j < mm) s[j] = dot8(qa, qb, pa[j], pb[j]);
            #pragma unroll
            for (int o = 16; o; o >>= 1)
                #pragma unroll
                for (int j = 0; j < 4; j++)
                    if (j < mm) s[j] += __shfl_xor_sync(0xffffffffu, s[j], o);
            if (lane == 0)
                #pragma unroll
                for (int j = 0; j < 4; j++)
                    if (j < mm) candd[w][i0 + j] = s[j];
        }
        __syncwarp();

        float dmax = candd[w][0];
        for (int i = 1; i < m; i++) dmax = fmaxf(dmax, candd[w][i]);
        float Xf = __fdiv_rn(dmax, 0.1f);

        double z = 0.0;
        for (int i = 0; i < m; i++) {
            float x = __fdiv_rn(candd[w][i], 0.1f);
            float e = expf(__fsub_rn(x, Xf));
            if (e >= FMINF) z += (double)e;
        }
        float Za = (float)z;

        bd = candd[w][0];
        for (int i = 0; i < m; i++) {
            int n = g_cand[(size_t)row * NC + i];
            float d = candd[w][i];
            float x = __fdiv_rn(d, 0.1f);
            float e = expf(__fsub_rn(x, Xf));
            if (e < FMINF) e = 0.f;
            float sc = __fdiv_rn(e, Za);
            if (sc < FMINF) sc = 0.f;
            float p = __fmul_rn(sc, g_w[b * NN + n]);
            if (p < FMINF) p = 0.f;
            if (p > bp || (p == bp && p > 0.f && n < bn)) {
                bp = p; bn = n; bd = d;
            }
        }
    } else {
        // overflow: full exact 512-proto scan (rare; always correct)
        #pragma unroll 1
        for (int n = 0; n < NN; n++) {
            const float4* p4 = (const float4*)(P + n * CCH);
            float s = warp_sumf(dot8(qa, qb, p4[lane], p4[lane + 32]));
            if (lane == 0) ovf[w][n] = s;
        }
        __syncwarp();
        float dmax = -INFINITY;
        for (int n = 0; n < NN; n++) dmax = fmaxf(dmax, ovf[w][n]);
        float Xf = __fdiv_rn(dmax, 0.1f);
        double z = 0.0;
        for (int n = 0; n < NN; n++) {
            float x = __fdiv_rn(ovf[w][n], 0.1f);
            float e = expf(__fsub_rn(x, Xf));
            if (e >= FMINF) z += (double)e;
        }
        float Za = (float)z;
        bd = ovf[w][0];
        for (int n = 0; n < NN; n++) {
            float d = ovf[w][n];
            float x = __fdiv_rn(d, 0.1f);
            float e = expf(__fsub_rn(x, Xf));
            if (e < FMINF) e = 0.f;
            float sc = __fdiv_rn(e, Za);
            if (sc < FMINF) sc = 0.f;
            float p = __fmul_rn(sc, g_w[b * NN + n]);
            if (p < FMINF) p = 0.f;
            if (p > bp) { bp = p; bn = n; bd = d; }
        }
    }

    if (lane == 0)
        out[row] = fmaf(-2.0f, bd, g_qq[row]) + g_pn2[bn];
}

// ---------------------------------------------------------------------------
extern "C" void kernel_launch(void* const* d_in, const int* in_sizes, int n_in,
                              void* d_out, int out_size) {
    const float* Q = nullptr;
    const float* P = nullptr;
    const float* G = nullptr;
    for (int i = 0; i < n_in; i++) {
        if (in_sizes[i] == BB * LL * CCH) Q = (const float*)d_in[i];
        else if (in_sizes[i] == NN * CCH) P = (const float*)d_in[i];
        else if (in_sizes[i] == BB * KK * CCH) G = (const float*)d_in[i];
    }
    float* out = (float*)d_out;

    prep_w_kernel<<<BB, 256>>>(P, G);
    prep_pz_kernel<<<NN / 8, 256>>>(P);
    prep_qz_kernel<<<BB * LL / 8, 256>>>(Q);
    filter_kernel<<<BB * LL / 16, 256>>>(out);
    refine_kernel<<<BB * LL / 8, 256>>>(Q, P, out);
}

// round 17
// speedup vs baseline: 1.3847x; 1.3847x over previous
#include <cuda_runtime.h>
#include <cuda_bf16.h>
#include <math.h>

#define BB 8
#define LL 8192
#define CCH 256
#define NN 512
#define KK 16
#define FMINF 1.17549435e-38f
#define NC 24

// scratch (no allocations allowed)
__device__ float g_w[BB * NN];               // FTZ proto_weights
__device__ float g_pn2[NN];                  // |p_n|^2
__device__ float g_qq[BB * LL];              // |q_l|^2
__device__ unsigned g_Pz[NN * 128];          // bf16x2, fragment-permuted P
__device__ unsigned g_Qz[BB * LL * 128];     // bf16x2, fragment-permuted Q (32MB)
__device__ int g_cc[BB * LL];                // per-row candidate count
__device__ int g_cand[BB * LL * NC];         // per-row candidate indices

__device__ __forceinline__ float warp_maxf(float v) {
    #pragma unroll
    for (int o = 16; o; o >>= 1) v = fmaxf(v, __shfl_xor_sync(0xffffffffu, v, o));
    return v;
}
__device__ __forceinline__ float warp_sumf(float v) {
    #pragma unroll
    for (int o = 16; o; o >>= 1) v += __shfl_xor_sync(0xffffffffu, v, o);
    return v;
}
__device__ __forceinline__ double warp_sumd(double v) {
    #pragma unroll
    for (int o = 16; o; o >>= 1) v += __shfl_xor_sync(0xffffffffu, v, o);
    return v;
}

__device__ __forceinline__ void mma_bf16(float& c0, float& c1, float& c2, float& c3,
                                         unsigned a0, unsigned a1, unsigned a2,
                                         unsigned a3, unsigned b0, unsigned b1) {
    asm volatile(
        "mma.sync.aligned.m16n8k16.row.col.f32.bf16.bf16.f32 "
        "{%0,%1,%2,%3}, {%4,%5,%6,%7}, {%8,%9}, {%0,%1,%2,%3};"
        : "+f"(c0), "+f"(c1), "+f"(c2), "+f"(c3)
        : "r"(a0), "r"(a1), "r"(a2), "r"(a3), "r"(b0), "r"(b1));
}

__device__ __forceinline__ float dot8(const float4& qa, const float4& qb,
                                      const float4& pa, const float4& pb) {
    float s = 0.f;
    s = fmaf(qa.x, pa.x, s); s = fmaf(qa.y, pa.y, s);
    s = fmaf(qa.z, pa.z, s); s = fmaf(qa.w, pa.w, s);
    s = fmaf(qb.x, pb.x, s); s = fmaf(qb.y, pb.y, s);
    s = fmaf(qb.z, pb.z, s); s = fmaf(qb.w, pb.w, s);
    return s;
}

__device__ __forceinline__ unsigned packbf(float x, float y) {
    __nv_bfloat162 h = __floats2bfloat162_rn(x, y);
    return *(unsigned*)&h;
}

// ---------------------------------------------------------------------------
// prep: per-batch FTZ proto weights (unchanged semantics)
// ---------------------------------------------------------------------------
__global__ void prep_w_kernel(const float* __restrict__ P,
                              const float* __restrict__ gt) {
    int b = blockIdx.x;
    int tid = threadIdx.x;
    int lane = tid & 31, wid = tid >> 5;
    __shared__ double gsd[CCH];
    __shared__ float xs[NN];
    __shared__ float redf[256];
    __shared__ double redd[256];
    __shared__ float sXmax, sZw;

    if (tid < CCH) {
        double s = 0.0;
        #pragma unroll
        for (int k = 0; k < KK; k++) s += (double)gt[(b * KK + k) * CCH + tid];
        gsd[tid] = (double)__fdiv_rn((float)s, 16.0f);
    }
    __syncthreads();

    for (int n = wid; n < NN; n += 8) {
        const float4* pr4 = (const float4*)(P + n * CCH);
        float4 v0 = pr4[lane];
        float4 v1 = pr4[lane + 32];
        int c0 = lane * 4, c1 = 128 + lane * 4;
        double a = 0.0;
        a = fma((double)v0.x, gsd[c0 + 0], a);
        a = fma((double)v0.y, gsd[c0 + 1], a);
        a = fma((double)v0.z, gsd[c0 + 2], a);
        a = fma((double)v0.w, gsd[c0 + 3], a);
        a = fma((double)v1.x, gsd[c1 + 0], a);
        a = fma((double)v1.y, gsd[c1 + 1], a);
        a = fma((double)v1.z, gsd[c1 + 2], a);
        a = fma((double)v1.w, gsd[c1 + 3], a);
        a = warp_sumd(a);
        if (lane == 0) xs[n] = __fdiv_rn((float)a, 0.1f);
    }
    __syncthreads();

    {
        float m = -INFINITY;
        for (int n = tid; n < NN; n += blockDim.x) m = fmaxf(m, xs[n]);
        redf[tid] = m;
        __syncthreads();
        for (int s = 128; s; s >>= 1) {
            if (tid < s) redf[tid] = fmaxf(redf[tid], redf[tid + s]);
            __syncthreads();
        }
        if (tid == 0) sXmax = redf[0];
        __syncthreads();
    }
    float X = sXmax;

    {
        double z = 0.0;
        for (int n = tid; n < NN; n += blockDim.x) {
            float e = expf(__fsub_rn(xs[n], X));
            if (e >= FMINF) z += (double)e;
        }
        redd[tid] = z;
        __syncthreads();
        for (int s = 128; s; s >>= 1) {
            if (tid < s) redd[tid] += redd[tid + s];
            __syncthreads();
        }
        if (tid == 0) sZw = (float)redd[0];
        __syncthreads();
    }
    float Zw = sZw;

    for (int n = tid; n < NN; n += blockDim.x) {
        float e = expf(__fsub_rn(xs[n], X));
        if (e < FMINF) e = 0.f;
        float w = __fdiv_rn(e, Zw);
        if (w < FMINF) w = 0.f;
        g_w[b * NN + n] = w;
    }
}

// ---------------------------------------------------------------------------
// prep: bf16-convert + fragment-permute P/Q (+ norms), coalesced via smem.
// ---------------------------------------------------------------------------
__global__ void prep_pz_kernel(const float* __restrict__ P) {
    __shared__ unsigned buf[8][128];
    int lane = threadIdx.x & 31, wid = threadIdx.x >> 5;
    int row = blockIdx.x * 8 + wid;
    const float4* p4 = (const float4*)(P + (size_t)row * CCH);
    float4 v0 = p4[lane], v1 = p4[lane + 32];
    float s = warp_sumf(dot8(v0, v1, v0, v1));
    if (lane == 0) g_pn2[row] = s;

    int gq = lane >> 2, f = lane & 3;
    int w1 = (f < 2) ? 4 * f : 4 * f - 7;
    int w2 = (f < 2) ? 4 * f + 2 : 4 * f - 5;
    buf[wid][gq * 8 + w1] = packbf(v0.x, v0.y);
    buf[wid][gq * 8 + w2] = packbf(v0.z, v0.w);
    buf[wid][(gq + 8) * 8 + w1] = packbf(v1.x, v1.y);
    buf[wid][(gq + 8) * 8 + w2] = packbf(v1.z, v1.w);
    __syncwarp();
    ((uint4*)(g_Pz + (size_t)row * 128))[lane] = ((const uint4*)buf[wid])[lane];
}

__global__ void prep_qz_kernel(const float* __restrict__ Q) {
    __shared__ unsigned buf[8][128];
    int lane = threadIdx.x & 31, wid = threadIdx.x >> 5;
    int row = blockIdx.x * 8 + wid;
    const float4* q4 = (const float4*)(Q + (size_t)row * CCH);
    float4 v0 = q4[lane], v1 = q4[lane + 32];
    float s = warp_sumf(dot8(v0, v1, v0, v1));
    if (lane == 0) g_qq[row] = s;

    int gq = lane >> 2, f = lane & 3;
    int w1 = (f < 2) ? 4 * f : 4 * f - 7;
    int w2 = (f < 2) ? 4 * f + 2 : 4 * f - 5;
    buf[wid][gq * 8 + w1] = packbf(v0.x, v0.y);
    buf[wid][gq * 8 + w2] = packbf(v0.z, v0.w);
    buf[wid][(gq + 8) * 8 + w1] = packbf(v1.x, v1.y);
    buf[wid][(gq + 8) * 8 + w2] = packbf(v1.z, v1.w);
    __syncwarp();
    ((uint4*)(g_Qz + (size_t)row * 128))[lane] = ((const uint4*)buf[wid])[lane];
}

// ---------------------------------------------------------------------------
// Filter kernel (unchanged, validated): bf16 mma, 16 rows x 512 protos/block.
// ---------------------------------------------------------------------------
struct __align__(16) FilterSmem {
    unsigned q_s[16][136];
    float dmS[8][16];
    int cnt[16];
    int cand[16][NC];
};

__global__ void __launch_bounds__(256, 3)
filter_kernel() {
    __shared__ FilterSmem S;

    int tid = threadIdx.x;
    int lane = tid & 31, w = tid >> 5;
    int g = lane >> 2, q = lane & 3;

    int R0 = blockIdx.x * 16;

    #pragma unroll
    for (int r = 0; r < 2; r++) {
        int idx = tid + r * 256;
        int l = idx >> 5, j = idx & 31;
        uint4 v = ((const uint4*)(g_Qz + (size_t)(R0 + l) * 128))[j];
        *(uint4*)&S.q_s[l][j * 4] = v;
    }
    if (tid < 16) { S.cnt[tid] = 1; S.cand[tid][0] = 0; }
    __syncthreads();

    float acc[8][4];
    #pragma unroll
    for (int ns = 0; ns < 8; ns++)
        #pragma unroll
        for (int e = 0; e < 4; e++) acc[ns][e] = 0.f;

    #pragma unroll 1
    for (int cc = 0; cc < 8; cc++) {
        #pragma unroll
        for (int grp = 0; grp < 2; grp++) {
            int wo = cc * 16 + grp * 8 + 2 * q;
            uint2 Bv[8];
            #pragma unroll
            for (int ns = 0; ns < 8; ns++) {
                int n = w * 64 + ns * 8 + g;
                Bv[ns] = __ldg((const uint2*)(g_Pz + (size_t)n * 128 + wo));
            }
            uint2 A0 = *(const uint2*)&S.q_s[g][wo];
            uint2 A1 = *(const uint2*)&S.q_s[g + 8][wo];
            #pragma unroll
            for (int ns = 0; ns < 8; ns++)
                mma_bf16(acc[ns][0], acc[ns][1], acc[ns][2], acc[ns][3],
                         A0.x, A1.x, A0.y, A1.y, Bv[ns].x, Bv[ns].y);
        }
    }

    #pragma unroll
    for (int h = 0; h < 2; h++) {
        int r = 8 * h + g;
        float vm = -INFINITY;
        #pragma unroll
        for (int ns = 0; ns < 8; ns++)
            #pragma unroll
            for (int e = 0; e < 2; e++)
                vm = fmaxf(vm, acc[ns][2 * h + e]);
        vm = fmaxf(vm, __shfl_xor_sync(0xffffffffu, vm, 1));
        vm = fmaxf(vm, __shfl_xor_sync(0xffffffffu, vm, 2));
        if (q == 0) S.dmS[w][r] = vm;
    }
    __syncthreads();

    #pragma unroll
    for (int h = 0; h < 2; h++) {
        int r = 8 * h + g;
        float gdm = -INFINITY;
        #pragma unroll
        for (int o = 0; o < 8; o++) gdm = fmaxf(gdm, S.dmS[o][r]);
        float dthr = gdm - 9.9f;
        #pragma unroll
        for (int ns = 0; ns < 8; ns++)
            #pragma unroll
            for (int e = 0; e < 2; e++) {
                float v = acc[ns][2 * h + e];
                int n = w * 64 + ns * 8 + 2 * q + e;
                if (n != 0 && v > dthr) {
                    int slot = atomicAdd(&S.cnt[r], 1);
                    if (slot < NC) S.cand[r][slot] = n;
                }
            }
    }
    __syncthreads();

    if (tid < 16) g_cc[R0 + tid] = S.cnt[tid];
    for (int idx = tid; idx < 16 * NC; idx += 256) {
        int r = idx / NC, i = idx % NC;
        if (i < min(S.cnt[r], NC)) g_cand[(size_t)(R0 + r) * NC + i] = S.cand[r][i];
    }
}

// ---------------------------------------------------------------------------
// Refine kernel: one warp per row; 4 candidates concurrently via 8-lane
// groups, each lane covering float4 indices t+8j (FULL 256 floats).
// Exact f32 dots + FTZ chain. Overflow -> register-resident full scan.
// ---------------------------------------------------------------------------
__global__ void __launch_bounds__(256)
refine_kernel(const float* __restrict__ Q, const float* __restrict__ P,
              float* __restrict__ out) {
    __shared__ float candd[8][NC];

    int lane = threadIdx.x & 31, w = threadIdx.x >> 5;
    int row = blockIdx.x * 8 + w;
    int b = row >> 13;
    int cntr = g_cc[row];
    int g = lane >> 3, t = lane & 7;

    const float4* q4 = (const float4*)(Q + (size_t)row * CCH);

    int bn = 0;
    float bp = 0.f;
    float bd;

    if (cntr <= NC) {
        int m = cntr;
        // lane's q slice: float4 indices t+8j, j=0..7 (full row across 8 lanes)
        float4 qv[8];
        #pragma unroll
        for (int j = 0; j < 8; j++) qv[j] = q4[t + 8 * j];

        #pragma unroll 1
        for (int i0 = 0; i0 < m; i0 += 4) {
            int i = i0 + g;
            int ci = (i < m) ? g_cand[(size_t)row * NC + i] : 0;
            const float4* p4 = (const float4*)(P + ci * CCH);
            float4 pv[8];
            #pragma unroll
            for (int j = 0; j < 8; j++) pv[j] = p4[t + 8 * j];   // MLP=8
            float s = 0.f;
            #pragma unroll
            for (int j = 0; j < 8; j++) {
                s = fmaf(qv[j].x, pv[j].x, s);
                s = fmaf(qv[j].y, pv[j].y, s);
                s = fmaf(qv[j].z, pv[j].z, s);
                s = fmaf(qv[j].w, pv[j].w, s);
            }
            s += __shfl_xor_sync(0xffffffffu, s, 1);
            s += __shfl_xor_sync(0xffffffffu, s, 2);
            s += __shfl_xor_sync(0xffffffffu, s, 4);
            if (t == 0 && i < m) candd[w][i] = s;
        }
        __syncwarp();

        float dmax = candd[w][0];
        for (int i = 1; i < m; i++) dmax = fmaxf(dmax, candd[w][i]);
        float Xf = __fdiv_rn(dmax, 0.1f);

        double z = 0.0;
        for (int i = 0; i < m; i++) {
            float x = __fdiv_rn(candd[w][i], 0.1f);
            float e = expf(__fsub_rn(x, Xf));
            if (e >= FMINF) z += (double)e;
        }
        float Za = (float)z;

        bd = candd[w][0];
        for (int i = 0; i < m; i++) {
            int n = g_cand[(size_t)row * NC + i];
            float d = candd[w][i];
            float x = __fdiv_rn(d, 0.1f);
            float e = expf(__fsub_rn(x, Xf));
            if (e < FMINF) e = 0.f;
            float sc = __fdiv_rn(e, Za);
            if (sc < FMINF) sc = 0.f;
            float p = __fmul_rn(sc, g_w[b * NN + n]);
            if (p < FMINF) p = 0.f;
            if (p > bp || (p == bp && p > 0.f && n < bn)) {
                bp = p; bn = n; bd = d;
            }
        }
    } else {
        // overflow: full exact 512-proto scan, register-resident (rare).
        float dl[16];
        float4 qa = q4[lane], qb = q4[lane + 32];
        #pragma unroll 1
        for (int n = 0; n < NN; n++) {
            const float4* p4 = (const float4*)(P + n * CCH);
            float s = warp_sumf(dot8(qa, qb, p4[lane], p4[lane + 32]));
            if ((n & 31) == lane) dl[n >> 5] = s;
        }
        float dm = dl[0];
        #pragma unroll
        for (int k = 1; k < 16; k++) dm = fmaxf(dm, dl[k]);
        float dmax = warp_maxf(dm);
        float Xf = __fdiv_rn(dmax, 0.1f);
        double z = 0.0;
        #pragma unroll
        for (int k = 0; k < 16; k++) {
            float x = __fdiv_rn(dl[k], 0.1f);
            float e = expf(__fsub_rn(x, Xf));
            if (e >= FMINF) z += (double)e;
        }
        float Za = (float)warp_sumd(z);
        int ln = 0x7FFFFFFF;
        float lp = 0.f, ld = 0.f;
        #pragma unroll
        for (int k = 0; k < 16; k++) {
            int n = k * 32 + lane;
            float d = dl[k];
            float x = __fdiv_rn(d, 0.1f);
            float e = expf(__fsub_rn(x, Xf));
            if (e < FMINF) e = 0.f;
            float sc = __fdiv_rn(e, Za);
            if (sc < FMINF) sc = 0.f;
            float p = __fmul_rn(sc, g_w[b * NN + n]);
            if (p < FMINF) p = 0.f;
            if (p > lp || (p == lp && p > 0.f && n < ln)) {
                lp = p; ln = n; ld = d;
            }
        }
        #pragma unroll
        for (int o = 16; o; o >>= 1) {
            float p2 = __shfl_xor_sync(0xffffffffu, lp, o);
            int n2 = __shfl_xor_sync(0xffffffffu, ln, o);
            float d2 = __shfl_xor_sync(0xffffffffu, ld, o);
            if (p2 > lp || (p2 == lp && p2 > 0.f && n2 < ln)) {
                lp = p2; ln = n2; ld = d2;
            }
        }
        float d0 = __shfl_sync(0xffffffffu, dl[0], 0);
        if (lp > 0.f) { bp = lp; bn = ln; bd = ld; }
        else { bn = 0; bd = d0; }
    }

    if (lane == 0)
        out[row] = fmaf(-2.0f, bd, g_qq[row]) + g_pn2[bn];
}

// ---------------------------------------------------------------------------
extern "C" void kernel_launch(void* const* d_in, const int* in_sizes, int n_in,
                              void* d_out, int out_size) {
    const float* Q = nullptr;
    const float* P = nullptr;
    const float* G = nullptr;
    for (int i = 0; i < n_in; i++) {
        if (in_sizes[i] == BB * LL * CCH) Q = (const float*)d_in[i];
        else if (in_sizes[i] == NN * CCH) P = (const float*)d_in[i];
        else if (in_sizes[i] == BB * KK * CCH) G = (const float*)d_in[i];
    }
    float* out = (float*)d_out;

    prep_w_kernel<<<BB, 256>>>(P, G);
    prep_pz_kernel<<<NN / 8, 256>>>(P);
    prep_qz_kernel<<<BB * LL / 8, 256>>>(Q);
    filter_kernel<<<BB * LL / 16, 256>>>();
    refine_kernel<<<BB * LL / 8, 256>>>(Q, P, out);
}